// round 5
// baseline (speedup 1.0000x reference)
#include <cuda_runtime.h>
#include <cuda_bf16.h>
#include <cstdint>

// Problem constants
#define B_  64
#define H_  128
#define W_  128
#define C_  3
#define KH_ 5
#define KW_ 5
#define N_  10
#define PAD_ 2
#define HW_ (H_ * W_)

#define SROW_ 136               // padded smem row length (cols -2..129 -> 0..131, pad to 136)
#define ROWS_ 8                 // smem image rows: h0-2 .. h0+5

__device__ __forceinline__ unsigned long long pk2(float lo, float hi) {
    unsigned long long r;
    asm("mov.b64 %0, {%1, %2};" : "=l"(r) : "f"(lo), "f"(hi));
    return r;
}
__device__ __forceinline__ unsigned long long ffma2(unsigned long long a,
                                                    unsigned long long b,
                                                    unsigned long long c) {
    unsigned long long d;
    asm("fma.rn.f32x2 %0, %1, %2, %3;" : "=l"(d) : "l"(a), "l"(b), "l"(c));
    return d;
}
__device__ __forceinline__ float lo32(unsigned long long p) {
    float f; asm("{ .reg .f32 t; mov.b64 {%0, t}, %1; }" : "=f"(f) : "l"(p)); return f;
}
__device__ __forceinline__ float hi32(unsigned long long p) {
    float f; asm("{ .reg .f32 t; mov.b64 {t, %0}, %1; }" : "=f"(f) : "l"(p)); return f;
}

// f32x2 lanes = two horizontally adjacent pixels (w0, w0+1).
// Weights pre-duplicated in smem -> broadcast loads, zero dup-movs.
// Image channel-planar in smem -> aligned LDS.64 pairs (+2 repacks per dh,c).
// Block: 256 threads = 64 pixel-pairs (full 128-wide row) x 4 rows.
extern "C" __global__ void __launch_bounds__(256, 3)
cdna_apply_kernel(const float* __restrict__ images,
                  const float* __restrict__ kernels,
                  float* __restrict__ out) {
    const int b  = blockIdx.y;        // batch
    const int h0 = blockIdx.x * 4;    // first of 4 output rows this block owns

    // channel-planar image tile: [c][row][col]; col 0..131 = img col -2..129
    __shared__ __align__(16) float s_img[C_][ROWS_][SROW_];
    // duplicated weights: [tap][n] = (k,k) u64; tap row padded to 12 (96B, 16B-aligned)
    __shared__ __align__(16) unsigned long long s_kw[25][12];

    const int tid = threadIdx.x;
    const float* img = images  + (size_t)b * (H_ * W_ * C_);
    const float* ker = kernels + b * (KH_ * KW_ * N_);

    // --- zero-fill smem image (covers halos + padding) ---
    {
        float4* p = reinterpret_cast<float4*>(&s_img[0][0][0]);
        const int n4 = (C_ * ROWS_ * SROW_) / 4;   // 816
        for (int i = tid; i < n4; i += 256) p[i] = make_float4(0.f, 0.f, 0.f, 0.f);
    }
    // duplicated weights
    if (tid < 250) {
        const int tap = tid / 10;
        const int n   = tid - tap * 10;
        const float v = ker[tid];
        s_kw[tap][n] = pk2(v, v);
    }
    __syncthreads();

    // --- fill interior: gmem [row][col][c] -> planar [c][row][col+2] ---
    for (int i = tid; i < ROWS_ * W_ * C_; i += 256) {
        const int r   = i / (W_ * C_);
        const int rem = i - r * (W_ * C_);
        const int col = rem / C_;
        const int c   = rem - col * C_;
        const int gr  = h0 - 2 + r;
        if ((unsigned)gr < (unsigned)H_)
            s_img[c][r][col + 2] = img[gr * (W_ * C_) + rem];
    }
    __syncthreads();

    const int pi = tid & 63;    // pixel-pair index; pixels w0, w0+1
    const int hr = tid >> 6;    // row within block (0..3)
    const int w0 = pi * 2;

    // acc[n][c]: f32x2 lanes = (pixel w0, pixel w0+1)
    unsigned long long acc[N_][C_];
#pragma unroll
    for (int n = 0; n < N_; ++n)
#pragma unroll
        for (int c = 0; c < C_; ++c) acc[n][c] = 0ull;

    for (int dh = 0; dh < 5; ++dh) {
        // image pairs for this dh: per c, 3 aligned LDS.64 + 2 repacks -> 5 dw shifts
        unsigned long long iv[5][C_];
#pragma unroll
        for (int c = 0; c < C_; ++c) {
            const float* row = &s_img[c][hr + dh][w0];
            const unsigned long long P0 = *reinterpret_cast<const unsigned long long*>(row);     // cols w0,w0+1   (dw=0)
            const unsigned long long P1 = *reinterpret_cast<const unsigned long long*>(row + 2); // cols w0+2,w0+3 (dw=2)
            const unsigned long long P2 = *reinterpret_cast<const unsigned long long*>(row + 4); // cols w0+4,w0+5 (dw=4)
            iv[0][c] = P0;
            iv[1][c] = pk2(hi32(P0), lo32(P1));   // (dw=1)
            iv[2][c] = P1;
            iv[3][c] = pk2(hi32(P1), lo32(P2));   // (dw=3)
            iv[4][c] = P2;
        }
#pragma unroll
        for (int dw = 0; dw < 5; ++dw) {
            // duplicated weights: 2x LDS.128 + 1x LDS.64, all broadcast
            const unsigned long long* kt = &s_kw[dh * 5 + dw][0];
            const ulonglong2 kA = *reinterpret_cast<const ulonglong2*>(kt);      // n=0,1
            const ulonglong2 kB = *reinterpret_cast<const ulonglong2*>(kt + 2);  // n=2,3
            const ulonglong2 kC = *reinterpret_cast<const ulonglong2*>(kt + 4);  // n=4,5
            const ulonglong2 kD = *reinterpret_cast<const ulonglong2*>(kt + 6);  // n=6,7
            const ulonglong2 kE = *reinterpret_cast<const ulonglong2*>(kt + 8);  // n=8,9
#pragma unroll
            for (int c = 0; c < C_; ++c) {
                const unsigned long long v = iv[dw][c];
                acc[0][c] = ffma2(v, kA.x, acc[0][c]);
                acc[1][c] = ffma2(v, kA.y, acc[1][c]);
                acc[2][c] = ffma2(v, kB.x, acc[2][c]);
                acc[3][c] = ffma2(v, kB.y, acc[3][c]);
                acc[4][c] = ffma2(v, kC.x, acc[4][c]);
                acc[5][c] = ffma2(v, kC.y, acc[5][c]);
                acc[6][c] = ffma2(v, kD.x, acc[6][c]);
                acc[7][c] = ffma2(v, kD.y, acc[7][c]);
                acc[8][c] = ffma2(v, kE.x, acc[8][c]);
                acc[9][c] = ffma2(v, kE.y, acc[9][c]);
            }
        }
    }

    // --- store: out[n][b][c][h][w0..w0+1] -> STG.64, coalesced across warp ---
    const int hpix = h0 + hr;
    char* o0 = reinterpret_cast<char*>(out)
             + (((size_t)b * C_) * HW_ + hpix * W_ + w0) * sizeof(float);
#pragma unroll
    for (int n = 0; n < N_; ++n) {
        char* on = o0 + (size_t)n * (B_ * C_ * HW_) * sizeof(float);
#pragma unroll
        for (int c = 0; c < C_; ++c)
            *reinterpret_cast<unsigned long long*>(on + (size_t)c * HW_ * sizeof(float))
                = acc[n][c];
    }
}

extern "C" void kernel_launch(void* const* d_in, const int* in_sizes, int n_in,
                              void* d_out, int out_size) {
    const float* images  = (const float*)d_in[0];  // [64,128,128,3]
    const float* kernels = (const float*)d_in[1];  // [64,5,5,10]
    float* out = (float*)d_out;                    // [10,64,3,128,128]
    (void)in_sizes; (void)n_in; (void)out_size;

    dim3 grid(H_ / 4, B_);   // 32 x 64 blocks
    dim3 block(256);
    cdna_apply_kernel<<<grid, block>>>(images, kernels, out);
}

// round 7
// speedup vs baseline: 1.5610x; 1.5610x over previous
#include <cuda_runtime.h>
#include <cuda_bf16.h>
#include <cstdint>

// Problem constants
#define B_  64
#define H_  128
#define W_  128
#define C_  3
#define KH_ 5
#define KW_ 5
#define N_  10
#define PAD_ 2
#define HW_ (H_ * W_)

#define SCOL_ 132   // smem cols: img col -2..129 -> idx 0..131
#define SR_   6     // smem rows: h0-2 .. h0+3

__device__ __forceinline__ unsigned long long pk2(float lo, float hi) {
    unsigned long long r;
    asm("mov.b64 %0, {%1, %2};" : "=l"(r) : "f"(lo), "f"(hi));
    return r;
}
__device__ __forceinline__ void unpk2(unsigned long long p, float& lo, float& hi) {
    asm("mov.b64 {%0, %1}, %2;" : "=f"(lo), "=f"(hi) : "l"(p));
}
__device__ __forceinline__ unsigned long long ffma2(unsigned long long a,
                                                    unsigned long long b,
                                                    unsigned long long c) {
    unsigned long long d;
    asm("fma.rn.f32x2 %0, %1, %2, %3;" : "=l"(d) : "l"(a), "l"(b), "l"(c));
    return d;
}

// R4 structure (1 px/thread, 15 n-packed f32x2 accs, 4 CTAs/SM) but the image
// tile is stored in smem as PRE-DUPLICATED (v,v) u64 pairs, channel-planar.
// Image operand = one conflict-free LDS.64 broadcast-into-lanes; the 150
// per-thread dup-MOVs of R4 are gone.
extern "C" __global__ void __launch_bounds__(256, 4)
cdna_apply_kernel(const float* __restrict__ images,
                  const float* __restrict__ kernels,
                  float* __restrict__ out) {
    const int b  = blockIdx.y;        // batch
    const int h0 = blockIdx.x * 2;    // first of 2 output rows this block owns

    // image tile, channel-planar, each element duplicated (v,v)
    __shared__ __align__(16) unsigned long long s_img[C_][SR_][SCOL_];  // 19,008 B
    __shared__ __align__(16) float s_ker[25][12];                       // n-pairs, tap row padded

    const int tid = threadIdx.x;
    const float* img = images  + (size_t)b * (H_ * W_ * C_);
    const float* ker = kernels + b * (KH_ * KW_ * N_);

    // --- weights (n-contiguous pairs, as in R4) ---
    if (tid < 250) {
        const int tap = tid / 10;
        const int n   = tid - tap * 10;
        s_ker[tap][n] = ker[tid];
    }

    // --- zero-fill image tile (halo cols + out-of-range rows) ---
    for (int i = tid; i < C_ * SR_ * SCOL_; i += 256)
        (&s_img[0][0][0])[i] = 0ull;
    __syncthreads();

    // --- fill interior: gmem [row][col][c] -> planar dup [c][row][col+2] ---
    for (int i = tid; i < SR_ * W_ * C_; i += 256) {
        const int r   = i / (W_ * C_);
        const int rem = i - r * (W_ * C_);
        const int col = rem / C_;
        const int c   = rem - col * C_;
        const int gr  = h0 - 2 + r;
        if ((unsigned)gr < (unsigned)H_) {
            const float v = img[gr * (W_ * C_) + rem];
            s_img[c][r][col + 2] = pk2(v, v);
        }
    }
    __syncthreads();

    const int w  = tid & 127;   // output column
    const int hr = tid >> 7;    // row within block (0/1)

    // acc[n_pair][c] packed fp32x2 over n (lo = n=2j, hi = n=2j+1)
    unsigned long long acc[5][3];
#pragma unroll
    for (int j = 0; j < 5; ++j)
#pragma unroll
        for (int c = 0; c < 3; ++c) acc[j][c] = 0ull;

#pragma unroll
    for (int dh = 0; dh < 5; ++dh) {
#pragma unroll
        for (int dw = 0; dw < 5; ++dw) {
            // image operands: duplicated pairs, one LDS.64 each, zero movs
            const unsigned long long iv0 = s_img[0][hr + dh][w + dw];
            const unsigned long long iv1 = s_img[1][hr + dh][w + dw];
            const unsigned long long iv2 = s_img[2][hr + dh][w + dw];
            // weight n-pairs: 48B tap row -> LDS.128 + LDS.128 + LDS.64 (broadcast)
            const float* kp = &s_ker[dh * 5 + dw][0];
            const ulonglong2 wA = *reinterpret_cast<const ulonglong2*>(kp);      // pairs 0,1
            const ulonglong2 wB = *reinterpret_cast<const ulonglong2*>(kp + 4);  // pairs 2,3
            const unsigned long long w4 =
                *reinterpret_cast<const unsigned long long*>(kp + 8);            // pair 4

            acc[0][0] = ffma2(iv0, wA.x, acc[0][0]);
            acc[0][1] = ffma2(iv1, wA.x, acc[0][1]);
            acc[0][2] = ffma2(iv2, wA.x, acc[0][2]);
            acc[1][0] = ffma2(iv0, wA.y, acc[1][0]);
            acc[1][1] = ffma2(iv1, wA.y, acc[1][1]);
            acc[1][2] = ffma2(iv2, wA.y, acc[1][2]);
            acc[2][0] = ffma2(iv0, wB.x, acc[2][0]);
            acc[2][1] = ffma2(iv1, wB.x, acc[2][1]);
            acc[2][2] = ffma2(iv2, wB.x, acc[2][2]);
            acc[3][0] = ffma2(iv0, wB.y, acc[3][0]);
            acc[3][1] = ffma2(iv1, wB.y, acc[3][1]);
            acc[3][2] = ffma2(iv2, wB.y, acc[3][2]);
            acc[4][0] = ffma2(iv0, w4, acc[4][0]);
            acc[4][1] = ffma2(iv1, w4, acc[4][1]);
            acc[4][2] = ffma2(iv2, w4, acc[4][2]);
        }
    }

    // --- store: out[n][b][c][h][w], strength-reduced addressing ---
    const int hpix = h0 + hr;
    float* o = out + (size_t)b * (C_ * HW_) + hpix * W_ + w;  // n=0, c=0
#pragma unroll
    for (int j = 0; j < 5; ++j) {
        float* o_lo = o + (size_t)(2 * j)     * (B_ * C_ * HW_);
        float* o_hi = o + (size_t)(2 * j + 1) * (B_ * C_ * HW_);
#pragma unroll
        for (int c = 0; c < 3; ++c) {
            float lo, hi;
            unpk2(acc[j][c], lo, hi);
            o_lo[c * HW_] = lo;
            o_hi[c * HW_] = hi;
        }
    }
}

extern "C" void kernel_launch(void* const* d_in, const int* in_sizes, int n_in,
                              void* d_out, int out_size) {
    const float* images  = (const float*)d_in[0];  // [64,128,128,3]
    const float* kernels = (const float*)d_in[1];  // [64,5,5,10]
    float* out = (float*)d_out;                    // [10,64,3,128,128]
    (void)in_sizes; (void)n_in; (void)out_size;

    dim3 grid(H_ / 2, B_);   // 64 x 64 blocks
    dim3 block(256);
    cdna_apply_kernel<<<grid, block>>>(images, kernels, out);
}

// round 8
// speedup vs baseline: 1.5752x; 1.0090x over previous
#include <cuda_runtime.h>
#include <cuda_bf16.h>
#include <cstdint>

// Problem constants
#define B_  64
#define H_  128
#define W_  128
#define C_  3
#define KH_ 5
#define KW_ 5
#define N_  10
#define PAD_ 2
#define HW_ (H_ * W_)

#define SCOL_ 132   // smem cols: img col -2..129 -> idx 0..131
#define SR_   6     // smem rows: h0-2 .. h0+3

__device__ __forceinline__ unsigned long long pk2(float lo, float hi) {
    unsigned long long r;
    asm("mov.b64 %0, {%1, %2};" : "=l"(r) : "f"(lo), "f"(hi));
    return r;
}
__device__ __forceinline__ void unpk2(unsigned long long p, float& lo, float& hi) {
    asm("mov.b64 {%0, %1}, %2;" : "=f"(lo), "=f"(hi) : "l"(p));
}
__device__ __forceinline__ unsigned long long ffma2(unsigned long long a,
                                                    unsigned long long b,
                                                    unsigned long long c) {
    unsigned long long d;
    asm("fma.rn.f32x2 %0, %1, %2, %3;" : "=l"(d) : "l"(a), "l"(b), "l"(c));
    return d;
}

// R4 structure (1 px/thread, 15 n-packed f32x2 accs, 4 CTAs/SM) but the image
// tile is stored in smem as PRE-DUPLICATED (v,v) u64 pairs, channel-planar.
// Image operand = one conflict-free LDS.64 broadcast-into-lanes; the 150
// per-thread dup-MOVs of R4 are gone.
extern "C" __global__ void __launch_bounds__(256, 4)
cdna_apply_kernel(const float* __restrict__ images,
                  const float* __restrict__ kernels,
                  float* __restrict__ out) {
    const int b  = blockIdx.y;        // batch
    const int h0 = blockIdx.x * 2;    // first of 2 output rows this block owns

    // image tile, channel-planar, each element duplicated (v,v)
    __shared__ __align__(16) unsigned long long s_img[C_][SR_][SCOL_];  // 19,008 B
    __shared__ __align__(16) float s_ker[25][12];                       // n-pairs, tap row padded

    const int tid = threadIdx.x;
    const float* img = images  + (size_t)b * (H_ * W_ * C_);
    const float* ker = kernels + b * (KH_ * KW_ * N_);

    // --- weights (n-contiguous pairs, as in R4) ---
    if (tid < 250) {
        const int tap = tid / 10;
        const int n   = tid - tap * 10;
        s_ker[tap][n] = ker[tid];
    }

    // --- zero-fill image tile (halo cols + out-of-range rows) ---
    for (int i = tid; i < C_ * SR_ * SCOL_; i += 256)
        (&s_img[0][0][0])[i] = 0ull;
    __syncthreads();

    // --- fill interior: gmem [row][col][c] -> planar dup [c][row][col+2] ---
    for (int i = tid; i < SR_ * W_ * C_; i += 256) {
        const int r   = i / (W_ * C_);
        const int rem = i - r * (W_ * C_);
        const int col = rem / C_;
        const int c   = rem - col * C_;
        const int gr  = h0 - 2 + r;
        if ((unsigned)gr < (unsigned)H_) {
            const float v = img[gr * (W_ * C_) + rem];
            s_img[c][r][col + 2] = pk2(v, v);
        }
    }
    __syncthreads();

    const int w  = tid & 127;   // output column
    const int hr = tid >> 7;    // row within block (0/1)

    // acc[n_pair][c] packed fp32x2 over n (lo = n=2j, hi = n=2j+1)
    unsigned long long acc[5][3];
#pragma unroll
    for (int j = 0; j < 5; ++j)
#pragma unroll
        for (int c = 0; c < 3; ++c) acc[j][c] = 0ull;

#pragma unroll
    for (int dh = 0; dh < 5; ++dh) {
#pragma unroll
        for (int dw = 0; dw < 5; ++dw) {
            // image operands: duplicated pairs, one LDS.64 each, zero movs
            const unsigned long long iv0 = s_img[0][hr + dh][w + dw];
            const unsigned long long iv1 = s_img[1][hr + dh][w + dw];
            const unsigned long long iv2 = s_img[2][hr + dh][w + dw];
            // weight n-pairs: 48B tap row -> LDS.128 + LDS.128 + LDS.64 (broadcast)
            const float* kp = &s_ker[dh * 5 + dw][0];
            const ulonglong2 wA = *reinterpret_cast<const ulonglong2*>(kp);      // pairs 0,1
            const ulonglong2 wB = *reinterpret_cast<const ulonglong2*>(kp + 4);  // pairs 2,3
            const unsigned long long w4 =
                *reinterpret_cast<const unsigned long long*>(kp + 8);            // pair 4

            acc[0][0] = ffma2(iv0, wA.x, acc[0][0]);
            acc[0][1] = ffma2(iv1, wA.x, acc[0][1]);
            acc[0][2] = ffma2(iv2, wA.x, acc[0][2]);
            acc[1][0] = ffma2(iv0, wA.y, acc[1][0]);
            acc[1][1] = ffma2(iv1, wA.y, acc[1][1]);
            acc[1][2] = ffma2(iv2, wA.y, acc[1][2]);
            acc[2][0] = ffma2(iv0, wB.x, acc[2][0]);
            acc[2][1] = ffma2(iv1, wB.x, acc[2][1]);
            acc[2][2] = ffma2(iv2, wB.x, acc[2][2]);
            acc[3][0] = ffma2(iv0, wB.y, acc[3][0]);
            acc[3][1] = ffma2(iv1, wB.y, acc[3][1]);
            acc[3][2] = ffma2(iv2, wB.y, acc[3][2]);
            acc[4][0] = ffma2(iv0, w4, acc[4][0]);
            acc[4][1] = ffma2(iv1, w4, acc[4][1]);
            acc[4][2] = ffma2(iv2, w4, acc[4][2]);
        }
    }

    // --- store: out[n][b][c][h][w], strength-reduced addressing ---
    const int hpix = h0 + hr;
    float* o = out + (size_t)b * (C_ * HW_) + hpix * W_ + w;  // n=0, c=0
#pragma unroll
    for (int j = 0; j < 5; ++j) {
        float* o_lo = o + (size_t)(2 * j)     * (B_ * C_ * HW_);
        float* o_hi = o + (size_t)(2 * j + 1) * (B_ * C_ * HW_);
#pragma unroll
        for (int c = 0; c < 3; ++c) {
            float lo, hi;
            unpk2(acc[j][c], lo, hi);
            o_lo[c * HW_] = lo;
            o_hi[c * HW_] = hi;
        }
    }
}

extern "C" void kernel_launch(void* const* d_in, const int* in_sizes, int n_in,
                              void* d_out, int out_size) {
    const float* images  = (const float*)d_in[0];  // [64,128,128,3]
    const float* kernels = (const float*)d_in[1];  // [64,5,5,10]
    float* out = (float*)d_out;                    // [10,64,3,128,128]
    (void)in_sizes; (void)n_in; (void)out_size;

    dim3 grid(H_ / 2, B_);   // 64 x 64 blocks
    dim3 block(256);
    cdna_apply_kernel<<<grid, block>>>(images, kernels, out);
}

// round 9
// speedup vs baseline: 1.8817x; 1.1946x over previous
#include <cuda_runtime.h>
#include <cuda_bf16.h>
#include <cstdint>

// Problem constants
#define B_  64
#define H_  128
#define W_  128
#define C_  3
#define KH_ 5
#define KW_ 5
#define N_  10
#define PAD_ 2
#define HW_ (H_ * W_)

#define RPB_   4     // output rows per block
#define FR_    8     // fill rows per block: h0-2 .. h0+5
#define SROWF_ 400   // smem floats per row: [2..7]=left halo, [8..391]=interior, [392..397]=right halo

__device__ __forceinline__ unsigned long long pk2(float lo, float hi) {
    unsigned long long r;
    asm("mov.b64 %0, {%1, %2};" : "=l"(r) : "f"(lo), "f"(hi));
    return r;
}
__device__ __forceinline__ void unpk2(unsigned long long p, float& lo, float& hi) {
    asm("mov.b64 {%0, %1}, %2;" : "=f"(lo), "=f"(hi) : "l"(p));
}
__device__ __forceinline__ unsigned long long ffma2(unsigned long long a,
                                                    unsigned long long b,
                                                    unsigned long long c) {
    unsigned long long d;
    asm("fma.rn.f32x2 %0, %1, %2, %3;" : "=l"(d) : "l"(a), "l"(b), "l"(c));
    return d;
}
__device__ __forceinline__ uint32_t smem_u32(const void* p) {
    uint32_t a;
    asm("{ .reg .u64 t; cvta.to.shared.u64 t, %1; cvt.u32.u64 %0, t; }" : "=r"(a) : "l"(p));
    return a;
}
__device__ __forceinline__ void cp_async16(uint32_t dst, const void* src) {
    asm volatile("cp.async.cg.shared.global [%0], [%1], 16;" :: "r"(dst), "l"(src) : "memory");
}

// R4 main-loop structure (1 px/thread, 15 n-packed f32x2 accs) with:
//  - 512-thread blocks covering 4 output rows (prologue amortized 2x, image
//    L2 rereads halved)
//  - interior image fill via cp.async 16B (no LDG->reg->STS latency)
// Img col x lives at smem float offset 8+3x (x in [-2,129]).
extern "C" __global__ void __launch_bounds__(512, 2)
cdna_apply_kernel(const float* __restrict__ images,
                  const float* __restrict__ kernels,
                  float* __restrict__ out) {
    const int b  = blockIdx.y;          // batch
    const int h0 = blockIdx.x * RPB_;   // first of 4 output rows this block owns

    __shared__ __align__(16) float s_img[FR_][SROWF_];  // 12,800 B
    __shared__ __align__(16) float s_ker[25][12];       // n-pairs, tap row padded

    const int tid = threadIdx.x;
    const float* img = images  + (size_t)b * (H_ * W_ * C_);
    const float* ker = kernels + b * (KH_ * KW_ * N_);

    // --- zero the whole image tile (covers halos + out-of-range rows) ---
    {
        float4* p = reinterpret_cast<float4*>(&s_img[0][0]);
        for (int i = tid; i < (FR_ * SROWF_) / 4; i += 512)   // 800 float4
            p[i] = make_float4(0.f, 0.f, 0.f, 0.f);
    }
    // weights (n-contiguous pairs)
    if (tid < 250) {
        const int tap = tid / 10;
        const int n   = tid - tap * 10;
        s_ker[tap][n] = ker[tid];
    }
    __syncthreads();

    // --- interior fill via cp.async: 8 rows x 96 float4 = 768 copies ---
    for (int i = tid; i < FR_ * 96; i += 512) {
        const int r    = i / 96;
        const int col4 = i - r * 96;
        const int gr   = h0 - 2 + r;
        if ((unsigned)gr < (unsigned)H_) {
            const uint32_t dst = smem_u32(&s_img[r][8 + col4 * 4]);
            cp_async16(dst, img + gr * (W_ * C_) + col4 * 4);
        }
    }
    asm volatile("cp.async.commit_group;" ::: "memory");
    asm volatile("cp.async.wait_group 0;" ::: "memory");
    __syncthreads();

    const int w  = tid & 127;   // output column
    const int hr = tid >> 7;    // row within block (0..3)

    // acc[n_pair][c] packed fp32x2 over n (lo = n=2j, hi = n=2j+1)
    unsigned long long acc[5][3];
#pragma unroll
    for (int j = 0; j < 5; ++j)
#pragma unroll
        for (int c = 0; c < 3; ++c) acc[j][c] = 0ull;

    // base: tap (dh,dw,c) at rowptr[dh*SROWF_ + dw*3 + c]
    const float* base = &s_img[hr][3 * w + 2];

#pragma unroll
    for (int dh = 0; dh < 5; ++dh) {
        const float* row = base + dh * SROWF_;
#pragma unroll
        for (int dw = 0; dw < 5; ++dw) {
            unsigned long long iv0, iv1, iv2;
            {
                const float v0 = row[dw * 3 + 0];
                const float v1 = row[dw * 3 + 1];
                const float v2 = row[dw * 3 + 2];
                iv0 = pk2(v0, v0);
                iv1 = pk2(v1, v1);
                iv2 = pk2(v2, v2);
            }
            const float* kp = &s_ker[dh * 5 + dw][0];
            const ulonglong2 wA = *reinterpret_cast<const ulonglong2*>(kp);      // pairs 0,1
            const ulonglong2 wB = *reinterpret_cast<const ulonglong2*>(kp + 4);  // pairs 2,3
            const unsigned long long w4 =
                *reinterpret_cast<const unsigned long long*>(kp + 8);            // pair 4

            acc[0][0] = ffma2(iv0, wA.x, acc[0][0]);
            acc[0][1] = ffma2(iv1, wA.x, acc[0][1]);
            acc[0][2] = ffma2(iv2, wA.x, acc[0][2]);
            acc[1][0] = ffma2(iv0, wA.y, acc[1][0]);
            acc[1][1] = ffma2(iv1, wA.y, acc[1][1]);
            acc[1][2] = ffma2(iv2, wA.y, acc[1][2]);
            acc[2][0] = ffma2(iv0, wB.x, acc[2][0]);
            acc[2][1] = ffma2(iv1, wB.x, acc[2][1]);
            acc[2][2] = ffma2(iv2, wB.x, acc[2][2]);
            acc[3][0] = ffma2(iv0, wB.y, acc[3][0]);
            acc[3][1] = ffma2(iv1, wB.y, acc[3][1]);
            acc[3][2] = ffma2(iv2, wB.y, acc[3][2]);
            acc[4][0] = ffma2(iv0, w4, acc[4][0]);
            acc[4][1] = ffma2(iv1, w4, acc[4][1]);
            acc[4][2] = ffma2(iv2, w4, acc[4][2]);
        }
    }

    // --- store: out[n][b][c][h][w], strength-reduced addressing ---
    const int hpix = h0 + hr;
    float* o = out + (size_t)b * (C_ * HW_) + hpix * W_ + w;  // n=0, c=0
#pragma unroll
    for (int j = 0; j < 5; ++j) {
        float* o_lo = o + (size_t)(2 * j)     * (B_ * C_ * HW_);
        float* o_hi = o + (size_t)(2 * j + 1) * (B_ * C_ * HW_);
#pragma unroll
        for (int c = 0; c < 3; ++c) {
            float lo, hi;
            unpk2(acc[j][c], lo, hi);
            o_lo[c * HW_] = lo;
            o_hi[c * HW_] = hi;
        }
    }
}

extern "C" void kernel_launch(void* const* d_in, const int* in_sizes, int n_in,
                              void* d_out, int out_size) {
    const float* images  = (const float*)d_in[0];  // [64,128,128,3]
    const float* kernels = (const float*)d_in[1];  // [64,5,5,10]
    float* out = (float*)d_out;                    // [10,64,3,128,128]
    (void)in_sizes; (void)n_in; (void)out_size;

    dim3 grid(H_ / RPB_, B_);   // 32 x 64 blocks
    dim3 block(512);
    cdna_apply_kernel<<<grid, block>>>(images, kernels, out);
}